// round 14
// baseline (speedup 1.0000x reference)
#include <cuda_runtime.h>
#include <cuda_fp16.h>
#include <mma.h>
#include <math.h>
#include <stdint.h>

using namespace nvcuda;

#define NUM_E 8
#define BATCH 4096
#define DIM   1024
#define DHID  4096

#define BM 256
#define BN 128
#define BK 32

// --- device scratch (no allocations allowed) ---
__device__ int    g_off[NUM_E + 1];
__device__ int    g_perm[BATCH];
__device__ __half g_hid[(size_t)BATCH * DHID];   // 32 MB, permuted rows, fp16
__device__ float  g_sscale[DIM];                 // sigmoid(scales)
__device__ float  g_cf, g_cy;                    // epilogue scalars

__device__ __forceinline__ float sigmoidf_(float x) { return 1.0f / (1.0f + expf(-x)); }

// ---------------- fused routing + epilogue-constant precompute ----------------
__device__ __forceinline__ int expert_of(float t) {
    int e = (int)(t * 8.0f);
    if (e < 0) e = 0;
    if (e > NUM_E - 1) e = NUM_E - 1;
    return e;
}

__global__ void k_route(const float* __restrict__ t, const float* __restrict__ scales,
                        const float* __restrict__ shifta, const float* __restrict__ shiftb) {
    __shared__ int s_cnt[NUM_E], s_cur[NUM_E];
    const int tid = threadIdx.x;
    if (tid < NUM_E) s_cnt[tid] = 0;

    // precompute sigmoid(scales) — exactly one element per thread (blockDim=1024=DIM)
    g_sscale[tid] = sigmoidf_(scales[tid]);
    if (tid == 0) {
        float s_a = sigmoidf_(shifta[0]);
        float s_b = sigmoidf_(shiftb[0]);
        g_cf = 0.5f * (s_a + s_b);
        g_cy = 0.5f * (s_b - s_a);
    }
    __syncthreads();
    int e_[4];
#pragma unroll
    for (int i = 0; i < 4; i++) {
        e_[i] = expert_of(t[tid + i * 1024]);
        atomicAdd(&s_cnt[e_[i]], 1);
    }
    __syncthreads();
    if (tid == 0) {
        int s = 0;
        for (int e = 0; e < NUM_E; e++) { g_off[e] = s; s_cur[e] = s; s += s_cnt[e]; }
        g_off[NUM_E] = s;
    }
    __syncthreads();
#pragma unroll
    for (int i = 0; i < 4; i++) {
        int p = atomicAdd(&s_cur[e_[i]], 1);
        g_perm[p] = tid + i * 1024;
    }
}

__device__ __forceinline__ float tanh_fast(float x) {
    float r; asm("tanh.approx.f32 %0, %1;" : "=f"(r) : "f"(x)); return r;
}

__device__ __forceinline__ uint4 f8_to_h8(float4 a, float4 b) {
    __half2 h0 = __floats2half2_rn(a.x, a.y);
    __half2 h1 = __floats2half2_rn(a.z, a.w);
    __half2 h2 = __floats2half2_rn(b.x, b.y);
    __half2 h3 = __floats2half2_rn(b.z, b.w);
    uint4 r;
    r.x = *(uint32_t*)&h0; r.y = *(uint32_t*)&h1;
    r.z = *(uint32_t*)&h2; r.w = *(uint32_t*)&h3;
    return r;
}

// ---------------- fp16 WMMA tiles: 256x128x32, 8 warps (4m x 2n), warp = 64x64 ----------------
#define AS_STRIDE 40     // halves (80B rows, 16B-aligned)
#define BS_STRIDE 136    // halves (272B rows, 16B-aligned)

typedef wmma::fragment<wmma::matrix_a, 16, 16, 16, __half, wmma::row_major> FragA;
typedef wmma::fragment<wmma::matrix_b, 16, 16, 16, __half, wmma::row_major> FragB;
typedef wmma::fragment<wmma::accumulator, 16, 16, 16, float> FragC;

// GEMM1: g_hid[seg0+m][n] = half( tanh( y[perm[seg0+m]] . W1[e][:,n] + b1[e][n] ) )
__global__ __launch_bounds__(256, 1)
void k_gemm1(const float* __restrict__ y, const float* __restrict__ W1,
             const float* __restrict__ b1)
{
    const int e    = blockIdx.z;
    const int seg0 = g_off[e];
    const int cnt  = g_off[e + 1] - seg0;
    const int tm   = blockIdx.y;
    if (tm * BM >= cnt) return;
    const int tn = blockIdx.x;

    __shared__ __half As[BM * AS_STRIDE];   // 20 KB
    __shared__ __half Bs[BK * BS_STRIDE];   // 8.5 KB
    __shared__ float  Cs[8 * 256];          // 8 KB

    const int tid  = threadIdx.x;
    const int wid  = tid >> 5;
    const int lane = tid & 31;
    const int wm   = wid >> 1;   // 0..3
    const int wn   = wid & 1;    // 0..1

    // A loader: 4 slots/thread; slot = 8 halves along k.
    const float* asrc[4];
    int arow[4], ak8[4];
#pragma unroll
    for (int i = 0; i < 4; i++) {
        int lin = tid + i * 256;
        arow[i] = lin >> 2;
        ak8[i]  = (lin & 3) * 8;
        int gm  = tm * BM + arow[i];
        int sr  = (gm < cnt) ? g_perm[seg0 + gm] : g_perm[seg0];
        asrc[i] = y + (size_t)sr * DIM + ak8[i];
    }
    const float* bsrc[2];
    int bk[2], bn8[2];
    const float* Wbase = W1 + (size_t)e * DIM * DHID + (size_t)tn * BN;
#pragma unroll
    for (int i = 0; i < 2; i++) {
        int lin = tid + i * 256;
        bk[i]  = lin >> 4;
        bn8[i] = (lin & 15) * 8;
        bsrc[i] = Wbase + (size_t)bk[i] * DHID + bn8[i];
    }

    FragC acc[4][4];
#pragma unroll
    for (int i = 0; i < 4; i++)
#pragma unroll
        for (int j = 0; j < 4; j++) wmma::fill_fragment(acc[i][j], 0.0f);

    float4 pa[4][2], pb[2][2];
#pragma unroll
    for (int i = 0; i < 4; i++) {
        pa[i][0] = *(const float4*)(asrc[i]);
        pa[i][1] = *(const float4*)(asrc[i] + 4);
    }
#pragma unroll
    for (int i = 0; i < 2; i++) {
        pb[i][0] = *(const float4*)(bsrc[i]);
        pb[i][1] = *(const float4*)(bsrc[i] + 4);
    }

    const int nstage = DIM / BK;   // 32
    for (int kt = 0; kt < nstage; kt++) {
#pragma unroll
        for (int i = 0; i < 4; i++)
            *(uint4*)&As[arow[i] * AS_STRIDE + ak8[i]] = f8_to_h8(pa[i][0], pa[i][1]);
#pragma unroll
        for (int i = 0; i < 2; i++)
            *(uint4*)&Bs[bk[i] * BS_STRIDE + bn8[i]] = f8_to_h8(pb[i][0], pb[i][1]);
        __syncthreads();

        if (kt + 1 < nstage) {
            const int k0 = (kt + 1) * BK;
#pragma unroll
            for (int i = 0; i < 4; i++) {
                pa[i][0] = *(const float4*)(asrc[i] + k0);
                pa[i][1] = *(const float4*)(asrc[i] + k0 + 4);
            }
#pragma unroll
            for (int i = 0; i < 2; i++) {
                pb[i][0] = *(const float4*)(bsrc[i] + (size_t)k0 * DHID);
                pb[i][1] = *(const float4*)(bsrc[i] + (size_t)k0 * DHID + 4);
            }
        }

#pragma unroll
        for (int kk = 0; kk < 2; kk++) {
            FragA a[4];
            FragB b[4];
#pragma unroll
            for (int fm = 0; fm < 4; fm++)
                wmma::load_matrix_sync(a[fm], &As[(wm * 64 + fm * 16) * AS_STRIDE + kk * 16], AS_STRIDE);
#pragma unroll
            for (int fn = 0; fn < 4; fn++)
                wmma::load_matrix_sync(b[fn], &Bs[(kk * 16) * BS_STRIDE + wn * 64 + fn * 16], BS_STRIDE);
#pragma unroll
            for (int fm = 0; fm < 4; fm++)
#pragma unroll
                for (int fn = 0; fn < 4; fn++)
                    wmma::mma_sync(acc[fm][fn], a[fm], b[fn], acc[fm][fn]);
        }
        __syncthreads();
    }

    // epilogue: vectorized — 2 threads/row, 8 contiguous cols each
    float* cbuf = &Cs[wid * 256];
    const float* b1e = b1 + (size_t)e * DHID;
    const int r  = lane >> 1;
    const int c0 = (lane & 1) * 8;
#pragma unroll
    for (int fn = 0; fn < 4; fn++) {
        const int gcol = tn * BN + wn * 64 + fn * 16 + c0;
        const float4 bb0 = *(const float4*)&b1e[gcol];
        const float4 bb1 = *(const float4*)&b1e[gcol + 4];
#pragma unroll
        for (int fm = 0; fm < 4; fm++) {
            wmma::store_matrix_sync(cbuf, acc[fm][fn], 16, wmma::mem_row_major);
            __syncwarp();
            const int gm = tm * BM + wm * 64 + fm * 16 + r;
            if (gm < cnt) {
                float4 v0 = *(const float4*)&cbuf[r * 16 + c0];
                float4 v1 = *(const float4*)&cbuf[r * 16 + c0 + 4];
                v0.x = tanh_fast(v0.x + bb0.x); v0.y = tanh_fast(v0.y + bb0.y);
                v0.z = tanh_fast(v0.z + bb0.z); v0.w = tanh_fast(v0.w + bb0.w);
                v1.x = tanh_fast(v1.x + bb1.x); v1.y = tanh_fast(v1.y + bb1.y);
                v1.z = tanh_fast(v1.z + bb1.z); v1.w = tanh_fast(v1.w + bb1.w);
                *(uint4*)&g_hid[(size_t)(seg0 + gm) * DHID + gcol] = f8_to_h8(v0, v1);
            }
            __syncwarp();
        }
    }
}

// GEMM2 + epilogue: out[perm[m]] = cf*sscale*(hid.W2 + b2) + cy*y[perm[m]]
__global__ __launch_bounds__(256, 1)
void k_gemm2(const float* __restrict__ y, const float* __restrict__ W2,
             const float* __restrict__ b2, float* __restrict__ out)
{
    const int e    = blockIdx.z;
    const int seg0 = g_off[e];
    const int cnt  = g_off[e + 1] - seg0;
    const int tm   = blockIdx.y;
    if (tm * BM >= cnt) return;
    const int tn = blockIdx.x;

    __shared__ __half As[BM * AS_STRIDE];
    __shared__ __half Bs[BK * BS_STRIDE];
    __shared__ float  Cs[8 * 256];

    const int tid  = threadIdx.x;
    const int wid  = tid >> 5;
    const int lane = tid & 31;
    const int wm   = wid >> 1;
    const int wn   = wid & 1;

    const __half* asrc[4];
    int arow[4], ak8[4];
#pragma unroll
    for (int i = 0; i < 4; i++) {
        int lin = tid + i * 256;
        arow[i] = lin >> 2;
        ak8[i]  = (lin & 3) * 8;
        int gm  = tm * BM + arow[i];
        int rr  = (gm < cnt) ? gm : 0;
        asrc[i] = g_hid + (size_t)(seg0 + rr) * DHID + ak8[i];
    }
    const float* bsrc[2];
    int bk[2], bn8[2];
    const float* Wbase = W2 + (size_t)e * DHID * DIM + (size_t)tn * BN;
#pragma unroll
    for (int i = 0; i < 2; i++) {
        int lin = tid + i * 256;
        bk[i]  = lin >> 4;
        bn8[i] = (lin & 15) * 8;
        bsrc[i] = Wbase + (size_t)bk[i] * DIM + bn8[i];
    }

    FragC acc[4][4];
#pragma unroll
    for (int i = 0; i < 4; i++)
#pragma unroll
        for (int j = 0; j < 4; j++) wmma::fill_fragment(acc[i][j], 0.0f);

    uint4  pa[4];
    float4 pb[2][2];
#pragma unroll
    for (int i = 0; i < 4; i++) pa[i] = *(const uint4*)(asrc[i]);
#pragma unroll
    for (int i = 0; i < 2; i++) {
        pb[i][0] = *(const float4*)(bsrc[i]);
        pb[i][1] = *(const float4*)(bsrc[i] + 4);
    }

    const int nstage = DHID / BK;  // 128
    for (int kt = 0; kt < nstage; kt++) {
#pragma unroll
        for (int i = 0; i < 4; i++)
            *(uint4*)&As[arow[i] * AS_STRIDE + ak8[i]] = pa[i];
#pragma unroll
        for (int i = 0; i < 2; i++)
            *(uint4*)&Bs[bk[i] * BS_STRIDE + bn8[i]] = f8_to_h8(pb[i][0], pb[i][1]);
        __syncthreads();

        if (kt + 1 < nstage) {
            const int k0 = (kt + 1) * BK;
#pragma unroll
            for (int i = 0; i < 4; i++) pa[i] = *(const uint4*)(asrc[i] + k0);
#pragma unroll
            for (int i = 0; i < 2; i++) {
                pb[i][0] = *(const float4*)(bsrc[i] + (size_t)k0 * DIM);
                pb[i][1] = *(const float4*)(bsrc[i] + (size_t)k0 * DIM + 4);
            }
        }

#pragma unroll
        for (int kk = 0; kk < 2; kk++) {
            FragA a[4];
            FragB b[4];
#pragma unroll
            for (int fm = 0; fm < 4; fm++)
                wmma::load_matrix_sync(a[fm], &As[(wm * 64 + fm * 16) * AS_STRIDE + kk * 16], AS_STRIDE);
#pragma unroll
            for (int fn = 0; fn < 4; fn++)
                wmma::load_matrix_sync(b[fn], &Bs[(kk * 16) * BS_STRIDE + wn * 64 + fn * 16], BS_STRIDE);
#pragma unroll
            for (int fm = 0; fm < 4; fm++)
#pragma unroll
                for (int fn = 0; fn < 4; fn++)
                    wmma::mma_sync(acc[fm][fn], a[fm], b[fn], acc[fm][fn]);
        }
        __syncthreads();
    }

    // epilogue: vectorized
    const float cf = g_cf;
    const float cy = g_cy;
    float* cbuf = &Cs[wid * 256];
    const float* b2e = b2 + (size_t)e * DIM;
    const int r  = lane >> 1;
    const int c0 = (lane & 1) * 8;
#pragma unroll
    for (int fn = 0; fn < 4; fn++) {
        const int gcol = tn * BN + wn * 64 + fn * 16 + c0;
        const float4 bb0 = *(const float4*)&b2e[gcol];
        const float4 bb1 = *(const float4*)&b2e[gcol + 4];
        const float4 ss0 = *(const float4*)&g_sscale[gcol];
        const float4 ss1 = *(const float4*)&g_sscale[gcol + 4];
#pragma unroll
        for (int fm = 0; fm < 4; fm++) {
            wmma::store_matrix_sync(cbuf, acc[fm][fn], 16, wmma::mem_row_major);
            __syncwarp();
            const int gm = tm * BM + wm * 64 + fm * 16 + r;
            if (gm < cnt) {
                const int orow = g_perm[seg0 + gm];
                const float* yp = y   + (size_t)orow * DIM + gcol;
                float*       op = out + (size_t)orow * DIM + gcol;
                float4 v0 = *(const float4*)&cbuf[r * 16 + c0];
                float4 v1 = *(const float4*)&cbuf[r * 16 + c0 + 4];
                const float4 y0 = *(const float4*)(yp);
                const float4 y1 = *(const float4*)(yp + 4);
                float4 o0, o1;
                o0.x = cf * (ss0.x * (v0.x + bb0.x)) + cy * y0.x;
                o0.y = cf * (ss0.y * (v0.y + bb0.y)) + cy * y0.y;
                o0.z = cf * (ss0.z * (v0.z + bb0.z)) + cy * y0.z;
                o0.w = cf * (ss0.w * (v0.w + bb0.w)) + cy * y0.w;
                o1.x = cf * (ss1.x * (v1.x + bb1.x)) + cy * y1.x;
                o1.y = cf * (ss1.y * (v1.y + bb1.y)) + cy * y1.y;
                o1.z = cf * (ss1.z * (v1.z + bb1.z)) + cy * y1.z;
                o1.w = cf * (ss1.w * (v1.w + bb1.w)) + cy * y1.w;
                *(float4*)(op)     = o0;
                *(float4*)(op + 4) = o1;
            }
            __syncwarp();
        }
    }
}

// ---------------- launch ----------------
extern "C" void kernel_launch(void* const* d_in, const int* in_sizes, int n_in,
                              void* d_out, int out_size)
{
    const float* t      = (const float*)d_in[0];
    const float* y      = (const float*)d_in[1];
    const float* W1     = (const float*)d_in[2];
    const float* b1     = (const float*)d_in[3];
    const float* W2     = (const float*)d_in[4];
    const float* b2     = (const float*)d_in[5];
    const float* scales = (const float*)d_in[6];
    const float* shifta = (const float*)d_in[7];
    const float* shiftb = (const float*)d_in[8];
    float* out = (float*)d_out;

    k_route<<<1, 1024>>>(t, scales, shifta, shiftb);

    dim3 g1(DHID / BN, (BATCH + BM - 1) / BM, NUM_E);
    k_gemm1<<<g1, 256>>>(y, W1, b1);

    dim3 g2(DIM / BN, (BATCH + BM - 1) / BM, NUM_E);
    k_gemm2<<<g2, 256>>>(y, W2, b2, out);
}

// round 15
// speedup vs baseline: 1.4505x; 1.4505x over previous
#include <cuda_runtime.h>
#include <cuda_fp16.h>
#include <mma.h>
#include <math.h>
#include <stdint.h>

using namespace nvcuda;

#define NUM_E 8
#define BATCH 4096
#define DIM   1024
#define DHID  4096

#define BM 256
#define BN 128
#define BK 32

// --- device scratch (no allocations allowed) ---
__device__ int    g_off[NUM_E + 1];
__device__ int    g_perm[BATCH];
__device__ __half g_hid[(size_t)BATCH * DHID];   // 32 MB, permuted rows, fp16
__device__ float  g_sscale[DIM];                 // sigmoid(scales)
__device__ float  g_cf, g_cy;                    // epilogue scalars

__device__ __forceinline__ float sigmoidf_(float x) { return 1.0f / (1.0f + expf(-x)); }

__device__ __forceinline__ float tanh_fast(float x) {
    float r; asm("tanh.approx.f32 %0, %1;" : "=f"(r) : "f"(x)); return r;
}

// ---------------- fused routing + epilogue-constant precompute ----------------
__device__ __forceinline__ int expert_of(float t) {
    int e = (int)(t * 8.0f);
    if (e < 0) e = 0;
    if (e > NUM_E - 1) e = NUM_E - 1;
    return e;
}

__global__ void k_route(const float* __restrict__ t, const float* __restrict__ scales,
                        const float* __restrict__ shifta, const float* __restrict__ shiftb) {
    __shared__ int s_cnt[NUM_E], s_cur[NUM_E];
    const int tid = threadIdx.x;
    if (tid < NUM_E) s_cnt[tid] = 0;

    // precompute sigmoid(scales) — one element per thread (blockDim = 1024 = DIM)
    g_sscale[tid] = sigmoidf_(scales[tid]);
    if (tid == 0) {
        float s_a = sigmoidf_(shifta[0]);
        float s_b = sigmoidf_(shiftb[0]);
        g_cf = 0.5f * (s_a + s_b);
        g_cy = 0.5f * (s_b - s_a);
    }
    __syncthreads();
    int e_[4];
#pragma unroll
    for (int i = 0; i < 4; i++) {
        e_[i] = expert_of(t[tid + i * 1024]);
        atomicAdd(&s_cnt[e_[i]], 1);
    }
    __syncthreads();
    if (tid == 0) {
        int s = 0;
        for (int e = 0; e < NUM_E; e++) { g_off[e] = s; s_cur[e] = s; s += s_cnt[e]; }
        g_off[NUM_E] = s;
    }
    __syncthreads();
#pragma unroll
    for (int i = 0; i < 4; i++) {
        int p = atomicAdd(&s_cur[e_[i]], 1);
        g_perm[p] = tid + i * 1024;
    }
}

__device__ __forceinline__ uint4 f8_to_h8(float4 a, float4 b) {
    __half2 h0 = __floats2half2_rn(a.x, a.y);
    __half2 h1 = __floats2half2_rn(a.z, a.w);
    __half2 h2 = __floats2half2_rn(b.x, b.y);
    __half2 h3 = __floats2half2_rn(b.z, b.w);
    uint4 r;
    r.x = *(uint32_t*)&h0; r.y = *(uint32_t*)&h1;
    r.z = *(uint32_t*)&h2; r.w = *(uint32_t*)&h3;
    return r;
}

// ---------------- fp16 WMMA tiles: 256x128x32, 8 warps (4m x 2n), warp = 64x64 ----------------
#define AS_STRIDE 40     // halves (80B rows, 16B-aligned)
#define BS_STRIDE 136    // halves (272B rows, 16B-aligned)

typedef wmma::fragment<wmma::matrix_a, 16, 16, 16, __half, wmma::row_major> FragA;
typedef wmma::fragment<wmma::matrix_b, 16, 16, 16, __half, wmma::row_major> FragB;
typedef wmma::fragment<wmma::accumulator, 16, 16, 16, float> FragC;

// GEMM1: g_hid[seg0+m][n] = half( tanh( y[perm[seg0+m]] . W1[e][:,n] + b1[e][n] ) )
__global__ __launch_bounds__(256, 1)
void k_gemm1(const float* __restrict__ y, const float* __restrict__ W1,
             const float* __restrict__ b1)
{
    const int e    = blockIdx.z;
    const int seg0 = g_off[e];
    const int cnt  = g_off[e + 1] - seg0;
    const int tm   = blockIdx.y;
    if (tm * BM >= cnt) return;
    const int tn = blockIdx.x;

    __shared__ __half As[BM * AS_STRIDE];   // 20 KB
    __shared__ __half Bs[BK * BS_STRIDE];   // 8.5 KB
    __shared__ float  Cs[8 * 256];          // 8 KB

    const int tid  = threadIdx.x;
    const int wid  = tid >> 5;
    const int lane = tid & 31;
    const int wm   = wid >> 1;   // 0..3
    const int wn   = wid & 1;    // 0..1

    // A loader: 4 slots/thread; slot = 8 halves along k.
    const float* asrc[4];
    int arow[4], ak8[4];
#pragma unroll
    for (int i = 0; i < 4; i++) {
        int lin = tid + i * 256;
        arow[i] = lin >> 2;
        ak8[i]  = (lin & 3) * 8;
        int gm  = tm * BM + arow[i];
        int sr  = (gm < cnt) ? g_perm[seg0 + gm] : g_perm[seg0];
        asrc[i] = y + (size_t)sr * DIM + ak8[i];
    }
    const float* bsrc[2];
    int bk[2], bn8[2];
    const float* Wbase = W1 + (size_t)e * DIM * DHID + (size_t)tn * BN;
#pragma unroll
    for (int i = 0; i < 2; i++) {
        int lin = tid + i * 256;
        bk[i]  = lin >> 4;
        bn8[i] = (lin & 15) * 8;
        bsrc[i] = Wbase + (size_t)bk[i] * DHID + bn8[i];
    }

    FragC acc[4][4];
#pragma unroll
    for (int i = 0; i < 4; i++)
#pragma unroll
        for (int j = 0; j < 4; j++) wmma::fill_fragment(acc[i][j], 0.0f);

    float4 pa[4][2], pb[2][2];
#pragma unroll
    for (int i = 0; i < 4; i++) {
        pa[i][0] = *(const float4*)(asrc[i]);
        pa[i][1] = *(const float4*)(asrc[i] + 4);
    }
#pragma unroll
    for (int i = 0; i < 2; i++) {
        pb[i][0] = *(const float4*)(bsrc[i]);
        pb[i][1] = *(const float4*)(bsrc[i] + 4);
    }

    const int nstage = DIM / BK;   // 32
    for (int kt = 0; kt < nstage; kt++) {
#pragma unroll
        for (int i = 0; i < 4; i++)
            *(uint4*)&As[arow[i] * AS_STRIDE + ak8[i]] = f8_to_h8(pa[i][0], pa[i][1]);
#pragma unroll
        for (int i = 0; i < 2; i++)
            *(uint4*)&Bs[bk[i] * BS_STRIDE + bn8[i]] = f8_to_h8(pb[i][0], pb[i][1]);
        __syncthreads();

        if (kt + 1 < nstage) {
            const int k0 = (kt + 1) * BK;
#pragma unroll
            for (int i = 0; i < 4; i++) {
                pa[i][0] = *(const float4*)(asrc[i] + k0);
                pa[i][1] = *(const float4*)(asrc[i] + k0 + 4);
            }
#pragma unroll
            for (int i = 0; i < 2; i++) {
                pb[i][0] = *(const float4*)(bsrc[i] + (size_t)k0 * DHID);
                pb[i][1] = *(const float4*)(bsrc[i] + (size_t)k0 * DHID + 4);
            }
        }

#pragma unroll
        for (int kk = 0; kk < 2; kk++) {
            FragA a[4];
            FragB b[4];
#pragma unroll
            for (int fm = 0; fm < 4; fm++)
                wmma::load_matrix_sync(a[fm], &As[(wm * 64 + fm * 16) * AS_STRIDE + kk * 16], AS_STRIDE);
#pragma unroll
            for (int fn = 0; fn < 4; fn++)
                wmma::load_matrix_sync(b[fn], &Bs[(kk * 16) * BS_STRIDE + wn * 64 + fn * 16], BS_STRIDE);
#pragma unroll
            for (int fm = 0; fm < 4; fm++)
#pragma unroll
                for (int fn = 0; fn < 4; fn++)
                    wmma::mma_sync(acc[fm][fn], a[fm], b[fn], acc[fm][fn]);
        }
        __syncthreads();
    }

    // epilogue: tanh(acc + b1) -> g_hid (half, permuted rows)  [round-13 structure]
    float* cbuf = &Cs[wid * 256];
    const float* b1e = b1 + (size_t)e * DHID;
#pragma unroll
    for (int fm = 0; fm < 4; fm++) {
#pragma unroll
        for (int fn = 0; fn < 4; fn++) {
            wmma::store_matrix_sync(cbuf, acc[fm][fn], 16, wmma::mem_row_major);
            __syncwarp();
#pragma unroll
            for (int j = 0; j < 8; j++) {
                int idx = lane + j * 32;
                int r = idx >> 4, c = idx & 15;
                int gm   = tm * BM + wm * 64 + fm * 16 + r;
                int gcol = tn * BN + wn * 64 + fn * 16 + c;
                if (gm < cnt)
                    g_hid[(size_t)(seg0 + gm) * DHID + gcol] =
                        __float2half_rn(tanh_fast(cbuf[idx] + b1e[gcol]));
            }
            __syncwarp();
        }
    }
}

// GEMM2 + epilogue: out[perm[m]] = cf*sscale*(hid.W2 + b2) + cy*y[perm[m]]
__global__ __launch_bounds__(256, 1)
void k_gemm2(const float* __restrict__ y, const float* __restrict__ W2,
             const float* __restrict__ b2, float* __restrict__ out)
{
    const int e    = blockIdx.z;
    const int seg0 = g_off[e];
    const int cnt  = g_off[e + 1] - seg0;
    const int tm   = blockIdx.y;
    if (tm * BM >= cnt) return;
    const int tn = blockIdx.x;

    __shared__ __half As[BM * AS_STRIDE];
    __shared__ __half Bs[BK * BS_STRIDE];
    __shared__ float  Cs[8 * 256];

    const int tid  = threadIdx.x;
    const int wid  = tid >> 5;
    const int lane = tid & 31;
    const int wm   = wid >> 1;
    const int wn   = wid & 1;

    const __half* asrc[4];
    int arow[4], ak8[4];
#pragma unroll
    for (int i = 0; i < 4; i++) {
        int lin = tid + i * 256;
        arow[i] = lin >> 2;
        ak8[i]  = (lin & 3) * 8;
        int gm  = tm * BM + arow[i];
        int rr  = (gm < cnt) ? gm : 0;
        asrc[i] = g_hid + (size_t)(seg0 + rr) * DHID + ak8[i];
    }
    const float* bsrc[2];
    int bk[2], bn8[2];
    const float* Wbase = W2 + (size_t)e * DHID * DIM + (size_t)tn * BN;
#pragma unroll
    for (int i = 0; i < 2; i++) {
        int lin = tid + i * 256;
        bk[i]  = lin >> 4;
        bn8[i] = (lin & 15) * 8;
        bsrc[i] = Wbase + (size_t)bk[i] * DIM + bn8[i];
    }

    FragC acc[4][4];
#pragma unroll
    for (int i = 0; i < 4; i++)
#pragma unroll
        for (int j = 0; j < 4; j++) wmma::fill_fragment(acc[i][j], 0.0f);

    uint4  pa[4];
    float4 pb[2][2];
#pragma unroll
    for (int i = 0; i < 4; i++) pa[i] = *(const uint4*)(asrc[i]);
#pragma unroll
    for (int i = 0; i < 2; i++) {
        pb[i][0] = *(const float4*)(bsrc[i]);
        pb[i][1] = *(const float4*)(bsrc[i] + 4);
    }

    const int nstage = DHID / BK;  // 128
    for (int kt = 0; kt < nstage; kt++) {
#pragma unroll
        for (int i = 0; i < 4; i++)
            *(uint4*)&As[arow[i] * AS_STRIDE + ak8[i]] = pa[i];
#pragma unroll
        for (int i = 0; i < 2; i++)
            *(uint4*)&Bs[bk[i] * BS_STRIDE + bn8[i]] = f8_to_h8(pb[i][0], pb[i][1]);
        __syncthreads();

        if (kt + 1 < nstage) {
            const int k0 = (kt + 1) * BK;
#pragma unroll
            for (int i = 0; i < 4; i++) pa[i] = *(const uint4*)(asrc[i] + k0);
#pragma unroll
            for (int i = 0; i < 2; i++) {
                pb[i][0] = *(const float4*)(bsrc[i] + (size_t)k0 * DIM);
                pb[i][1] = *(const float4*)(bsrc[i] + (size_t)k0 * DIM + 4);
            }
        }

#pragma unroll
        for (int kk = 0; kk < 2; kk++) {
            FragA a[4];
            FragB b[4];
#pragma unroll
            for (int fm = 0; fm < 4; fm++)
                wmma::load_matrix_sync(a[fm], &As[(wm * 64 + fm * 16) * AS_STRIDE + kk * 16], AS_STRIDE);
#pragma unroll
            for (int fn = 0; fn < 4; fn++)
                wmma::load_matrix_sync(b[fn], &Bs[(kk * 16) * BS_STRIDE + wn * 64 + fn * 16], BS_STRIDE);
#pragma unroll
            for (int fm = 0; fm < 4; fm++)
#pragma unroll
                for (int fn = 0; fn < 4; fn++)
                    wmma::mma_sync(acc[fm][fn], a[fm], b[fn], acc[fm][fn]);
        }
        __syncthreads();
    }

    // epilogue [round-13 structure, precomputed constants]
    const float cf = g_cf;
    const float cy = g_cy;
    float* cbuf = &Cs[wid * 256];
    const float* b2e = b2 + (size_t)e * DIM;
#pragma unroll
    for (int fm = 0; fm < 4; fm++) {
#pragma unroll
        for (int fn = 0; fn < 4; fn++) {
            wmma::store_matrix_sync(cbuf, acc[fm][fn], 16, wmma::mem_row_major);
            __syncwarp();
#pragma unroll
            for (int j = 0; j < 8; j++) {
                int idx = lane + j * 32;
                int r = idx >> 4, c = idx & 15;
                int gm   = tm * BM + wm * 64 + fm * 16 + r;
                int gcol = tn * BN + wn * 64 + fn * 16 + c;
                if (gm < cnt) {
                    int orow = g_perm[seg0 + gm];
                    float f = cbuf[idx] + b2e[gcol];
                    f = g_sscale[gcol] * f;
                    out[(size_t)orow * DIM + gcol] = cf * f + cy * y[(size_t)orow * DIM + gcol];
                }
            }
            __syncwarp();
        }
    }
}

// ---------------- launch ----------------
extern "C" void kernel_launch(void* const* d_in, const int* in_sizes, int n_in,
                              void* d_out, int out_size)
{
    const float* t      = (const float*)d_in[0];
    const float* y      = (const float*)d_in[1];
    const float* W1     = (const float*)d_in[2];
    const float* b1     = (const float*)d_in[3];
    const float* W2     = (const float*)d_in[4];
    const float* b2     = (const float*)d_in[5];
    const float* scales = (const float*)d_in[6];
    const float* shifta = (const float*)d_in[7];
    const float* shiftb = (const float*)d_in[8];
    float* out = (float*)d_out;

    k_route<<<1, 1024>>>(t, scales, shifta, shiftb);

    dim3 g1(DHID / BN, (BATCH + BM - 1) / BM, NUM_E);
    k_gemm1<<<g1, 256>>>(y, W1, b1);

    dim3 g2(DIM / BN, (BATCH + BM - 1) / BM, NUM_E);
    k_gemm2<<<g2, 256>>>(y, W2, b2, out);
}

// round 17
// speedup vs baseline: 1.4608x; 1.0071x over previous
#include <cuda_runtime.h>
#include <cuda_fp16.h>
#include <mma.h>
#include <math.h>
#include <stdint.h>

using namespace nvcuda;

#define NUM_E 8
#define BATCH 4096
#define DIM   1024
#define DHID  4096

#define BM 256
#define BN 128
#define BK 32

#define AS_STRIDE 40     // halves
#define BS_STRIDE 136    // halves
#define ASZ_H (BM * AS_STRIDE)                 // 10240 halves
#define BSZ_H (BK * BS_STRIDE)                 // 4352 halves
#define STAGE_H (ASZ_H + BSZ_H)                // 14592 halves
#define SMEM_BYTES (2 * STAGE_H * 2)           // 58368 bytes

// --- device scratch (no allocations allowed) ---
__device__ int    g_off[NUM_E + 1];
__device__ int    g_perm[BATCH];
__device__ __half g_hid[(size_t)BATCH * DHID];   // 32 MB, permuted rows, fp16
__device__ float  g_sscale[DIM];                 // sigmoid(scales)
__device__ float  g_cf, g_cy;                    // epilogue scalars

__device__ __forceinline__ float sigmoidf_(float x) { return 1.0f / (1.0f + expf(-x)); }

__device__ __forceinline__ float tanh_fast(float x) {
    float r; asm("tanh.approx.f32 %0, %1;" : "=f"(r) : "f"(x)); return r;
}

// ---------------- fused routing + epilogue-constant precompute ----------------
__device__ __forceinline__ int expert_of(float t) {
    int e = (int)(t * 8.0f);
    if (e < 0) e = 0;
    if (e > NUM_E - 1) e = NUM_E - 1;
    return e;
}

__global__ void k_route(const float* __restrict__ t, const float* __restrict__ scales,
                        const float* __restrict__ shifta, const float* __restrict__ shiftb) {
    __shared__ int s_cnt[NUM_E], s_cur[NUM_E];
    const int tid = threadIdx.x;
    if (tid < NUM_E) s_cnt[tid] = 0;

    g_sscale[tid] = sigmoidf_(scales[tid]);
    if (tid == 0) {
        float s_a = sigmoidf_(shifta[0]);
        float s_b = sigmoidf_(shiftb[0]);
        g_cf = 0.5f * (s_a + s_b);
        g_cy = 0.5f * (s_b - s_a);
    }
    __syncthreads();
    int e_[4];
#pragma unroll
    for (int i = 0; i < 4; i++) {
        e_[i] = expert_of(t[tid + i * 1024]);
        atomicAdd(&s_cnt[e_[i]], 1);
    }
    __syncthreads();
    if (tid == 0) {
        int s = 0;
        for (int e = 0; e < NUM_E; e++) { g_off[e] = s; s_cur[e] = s; s += s_cnt[e]; }
        g_off[NUM_E] = s;
    }
    __syncthreads();
#pragma unroll
    for (int i = 0; i < 4; i++) {
        int p = atomicAdd(&s_cur[e_[i]], 1);
        g_perm[p] = tid + i * 1024;
    }
}

__device__ __forceinline__ uint4 f8_to_h8(float4 a, float4 b) {
    __half2 h0 = __floats2half2_rn(a.x, a.y);
    __half2 h1 = __floats2half2_rn(a.z, a.w);
    __half2 h2 = __floats2half2_rn(b.x, b.y);
    __half2 h3 = __floats2half2_rn(b.z, b.w);
    uint4 r;
    r.x = *(uint32_t*)&h0; r.y = *(uint32_t*)&h1;
    r.z = *(uint32_t*)&h2; r.w = *(uint32_t*)&h3;
    return r;
}

typedef wmma::fragment<wmma::matrix_a, 16, 16, 16, __half, wmma::row_major> FragA;
typedef wmma::fragment<wmma::matrix_b, 16, 16, 16, __half, wmma::row_major> FragB;
typedef wmma::fragment<wmma::accumulator, 16, 16, 16, float> FragC;

// GEMM1: g_hid[seg0+m][n] = half( tanh( y[perm[seg0+m]] . W1[e][:,n] + b1[e][n] ) )
__global__ __launch_bounds__(256, 1)
void k_gemm1(const float* __restrict__ y, const float* __restrict__ W1,
             const float* __restrict__ b1)
{
    const int e    = blockIdx.z;
    const int seg0 = g_off[e];
    const int cnt  = g_off[e + 1] - seg0;
    const int tm   = blockIdx.y;
    if (tm * BM >= cnt) return;
    const int tn = blockIdx.x;

    extern __shared__ __half smh[];

    const int tid  = threadIdx.x;
    const int wid  = tid >> 5;
    const int lane = tid & 31;
    const int wm   = wid >> 1;   // 0..3
    const int wn   = wid & 1;    // 0..1

    // A loader: 4 slots/thread; slot = 8 halves along k.
    const float* asrc[4];
    int aoff[4];
#pragma unroll
    for (int i = 0; i < 4; i++) {
        int lin = tid + i * 256;
        int arow = lin >> 2;
        int ak8  = (lin & 3) * 8;
        aoff[i] = arow * AS_STRIDE + ak8;
        int gm  = tm * BM + arow;
        int sr  = (gm < cnt) ? g_perm[seg0 + gm] : g_perm[seg0];
        asrc[i] = y + (size_t)sr * DIM + ak8;
    }
    const float* bsrc[2];
    int boff[2];
    const float* Wbase = W1 + (size_t)e * DIM * DHID + (size_t)tn * BN;
#pragma unroll
    for (int i = 0; i < 2; i++) {
        int lin = tid + i * 256;
        int bk  = lin >> 4;
        int bn8 = (lin & 15) * 8;
        boff[i] = bk * BS_STRIDE + bn8;
        bsrc[i] = Wbase + (size_t)bk * DHID + bn8;
    }

    FragC acc[4][4];
#pragma unroll
    for (int i = 0; i < 4; i++)
#pragma unroll
        for (int j = 0; j < 4; j++) wmma::fill_fragment(acc[i][j], 0.0f);

    float4 pa[4][2], pb[2][2];
#pragma unroll
    for (int i = 0; i < 4; i++) {
        pa[i][0] = *(const float4*)(asrc[i]);
        pa[i][1] = *(const float4*)(asrc[i] + 4);
    }
#pragma unroll
    for (int i = 0; i < 2; i++) {
        pb[i][0] = *(const float4*)(bsrc[i]);
        pb[i][1] = *(const float4*)(bsrc[i] + 4);
    }

    const int nstage = DIM / BK;   // 32
    for (int kt = 0; kt < nstage; kt++) {
        __half* As = smh + (kt & 1) * STAGE_H;
        __half* Bs = As + ASZ_H;
#pragma unroll
        for (int i = 0; i < 4; i++)
            *(uint4*)&As[aoff[i]] = f8_to_h8(pa[i][0], pa[i][1]);
#pragma unroll
        for (int i = 0; i < 2; i++)
            *(uint4*)&Bs[boff[i]] = f8_to_h8(pb[i][0], pb[i][1]);
        __syncthreads();

        if (kt + 1 < nstage) {
            const int k0 = (kt + 1) * BK;
#pragma unroll
            for (int i = 0; i < 4; i++) {
                pa[i][0] = *(const float4*)(asrc[i] + k0);
                pa[i][1] = *(const float4*)(asrc[i] + k0 + 4);
            }
#pragma unroll
            for (int i = 0; i < 2; i++) {
                pb[i][0] = *(const float4*)(bsrc[i] + (size_t)k0 * DHID);
                pb[i][1] = *(const float4*)(bsrc[i] + (size_t)k0 * DHID + 4);
            }
        }

#pragma unroll
        for (int kk = 0; kk < 2; kk++) {
            FragA a[4];
            FragB b[4];
#pragma unroll
            for (int fm = 0; fm < 4; fm++)
                wmma::load_matrix_sync(a[fm], &As[(wm * 64 + fm * 16) * AS_STRIDE + kk * 16], AS_STRIDE);
#pragma unroll
            for (int fn = 0; fn < 4; fn++)
                wmma::load_matrix_sync(b[fn], &Bs[(kk * 16) * BS_STRIDE + wn * 64 + fn * 16], BS_STRIDE);
#pragma unroll
            for (int fm = 0; fm < 4; fm++)
#pragma unroll
                for (int fn = 0; fn < 4; fn++)
                    wmma::mma_sync(acc[fm][fn], a[fm], b[fn], acc[fm][fn]);
        }
        // no trailing sync: next store targets the other buffer
    }
    __syncthreads();   // smem reuse barrier before epilogue staging

    // epilogue: tanh(acc + b1) -> g_hid (half, permuted rows)
    float* cbuf = (float*)smh + wid * 256;
    const float* b1e = b1 + (size_t)e * DHID;
#pragma unroll
    for (int fm = 0; fm < 4; fm++) {
#pragma unroll
        for (int fn = 0; fn < 4; fn++) {
            wmma::store_matrix_sync(cbuf, acc[fm][fn], 16, wmma::mem_row_major);
            __syncwarp();
#pragma unroll
            for (int j = 0; j < 8; j++) {
                int idx = lane + j * 32;
                int r = idx >> 4, c = idx & 15;
                int gm   = tm * BM + wm * 64 + fm * 16 + r;
                int gcol = tn * BN + wn * 64 + fn * 16 + c;
                if (gm < cnt)
                    g_hid[(size_t)(seg0 + gm) * DHID + gcol] =
                        __float2half_rn(tanh_fast(cbuf[idx] + b1e[gcol]));
            }
            __syncwarp();
        }
    }
}

// GEMM2 + epilogue: out[perm[m]] = cf*sscale*(hid.W2 + b2) + cy*y[perm[m]]
__global__ __launch_bounds__(256, 1)
void k_gemm2(const float* __restrict__ y, const float* __restrict__ W2,
             const float* __restrict__ b2, float* __restrict__ out)
{
    const int e    = blockIdx.z;
    const int seg0 = g_off[e];
    const int cnt  = g_off[e + 1] - seg0;
    const int tm   = blockIdx.y;
    if (tm * BM >= cnt) return;
    const int tn = blockIdx.x;

    extern __shared__ __half smh[];

    const int tid  = threadIdx.x;
    const int wid  = tid >> 5;
    const int lane = tid & 31;
    const int wm   = wid >> 1;
    const int wn   = wid & 1;

    const __half* asrc[4];
    int aoff[4];
#pragma unroll
    for (int i = 0; i < 4; i++) {
        int lin = tid + i * 256;
        int arow = lin >> 2;
        int ak8  = (lin & 3) * 8;
        aoff[i] = arow * AS_STRIDE + ak8;
        int gm  = tm * BM + arow;
        int rr  = (gm < cnt) ? gm : 0;
        asrc[i] = g_hid + (size_t)(seg0 + rr) * DHID + ak8;
    }
    const float* bsrc[2];
    int boff[2];
    const float* Wbase = W2 + (size_t)e * DHID * DIM + (size_t)tn * BN;
#pragma unroll
    for (int i = 0; i < 2; i++) {
        int lin = tid + i * 256;
        int bk  = lin >> 4;
        int bn8 = (lin & 15) * 8;
        boff[i] = bk * BS_STRIDE + bn8;
        bsrc[i] = Wbase + (size_t)bk * DIM + bn8;
    }

    FragC acc[4][4];
#pragma unroll
    for (int i = 0; i < 4; i++)
#pragma unroll
        for (int j = 0; j < 4; j++) wmma::fill_fragment(acc[i][j], 0.0f);

    uint4  pa[4];
    float4 pb[2][2];
#pragma unroll
    for (int i = 0; i < 4; i++) pa[i] = *(const uint4*)(asrc[i]);
#pragma unroll
    for (int i = 0; i < 2; i++) {
        pb[i][0] = *(const float4*)(bsrc[i]);
        pb[i][1] = *(const float4*)(bsrc[i] + 4);
    }

    const int nstage = DHID / BK;  // 128
    for (int kt = 0; kt < nstage; kt++) {
        __half* As = smh + (kt & 1) * STAGE_H;
        __half* Bs = As + ASZ_H;
#pragma unroll
        for (int i = 0; i < 4; i++)
            *(uint4*)&As[aoff[i]] = pa[i];
#pragma unroll
        for (int i = 0; i < 2; i++)
            *(uint4*)&Bs[boff[i]] = f8_to_h8(pb[i][0], pb[i][1]);
        __syncthreads();

        if (kt + 1 < nstage) {
            const int k0 = (kt + 1) * BK;
#pragma unroll
            for (int i = 0; i < 4; i++) pa[i] = *(const uint4*)(asrc[i] + k0);
#pragma unroll
            for (int i = 0; i < 2; i++) {
                pb[i][0] = *(const float4*)(bsrc[i] + (size_t)k0 * DIM);
                pb[i][1] = *(const float4*)(bsrc[i] + (size_t)k0 * DIM + 4);
            }
        }

#pragma unroll
        for (int kk = 0; kk < 2; kk++) {
            FragA a[4];
            FragB b[4];
#pragma unroll
            for (int fm = 0; fm < 4; fm++)
                wmma::load_matrix_sync(a[fm], &As[(wm * 64 + fm * 16) * AS_STRIDE + kk * 16], AS_STRIDE);
#pragma unroll
            for (int fn = 0; fn < 4; fn++)
                wmma::load_matrix_sync(b[fn], &Bs[(kk * 16) * BS_STRIDE + wn * 64 + fn * 16], BS_STRIDE);
#pragma unroll
            for (int fm = 0; fm < 4; fm++)
#pragma unroll
                for (int fn = 0; fn < 4; fn++)
                    wmma::mma_sync(acc[fm][fn], a[fm], b[fn], acc[fm][fn]);
        }
        // no trailing sync: ping-pong
    }
    __syncthreads();

    // epilogue
    const float cf = g_cf;
    const float cy = g_cy;
    float* cbuf = (float*)smh + wid * 256;
    const float* b2e = b2 + (size_t)e * DIM;
#pragma unroll
    for (int fm = 0; fm < 4; fm++) {
#pragma unroll
        for (int fn = 0; fn < 4; fn++) {
            wmma::store_matrix_sync(cbuf, acc[fm][fn], 16, wmma::mem_row_major);
            __syncwarp();
#pragma unroll
            for (int j = 0; j < 8; j++) {
                int idx = lane + j * 32;
                int r = idx >> 4, c = idx & 15;
                int gm   = tm * BM + wm * 64 + fm * 16 + r;
                int gcol = tn * BN + wn * 64 + fn * 16 + c;
                if (gm < cnt) {
                    int orow = g_perm[seg0 + gm];
                    float f = cbuf[idx] + b2e[gcol];
                    f = g_sscale[gcol] * f;
                    out[(size_t)orow * DIM + gcol] = cf * f + cy * y[(size_t)orow * DIM + gcol];
                }
            }
            __syncwarp();
        }
    }
}

// ---------------- launch ----------------
extern "C" void kernel_launch(void* const* d_in, const int* in_sizes, int n_in,
                              void* d_out, int out_size)
{
    const float* t      = (const float*)d_in[0];
    const float* y      = (const float*)d_in[1];
    const float* W1     = (const float*)d_in[2];
    const float* b1     = (const float*)d_in[3];
    const float* W2     = (const float*)d_in[4];
    const float* b2     = (const float*)d_in[5];
    const float* scales = (const float*)d_in[6];
    const float* shifta = (const float*)d_in[7];
    const float* shiftb = (const float*)d_in[8];
    float* out = (float*)d_out;

    cudaFuncSetAttribute(k_gemm1, cudaFuncAttributeMaxDynamicSharedMemorySize, SMEM_BYTES);
    cudaFuncSetAttribute(k_gemm2, cudaFuncAttributeMaxDynamicSharedMemorySize, SMEM_BYTES);

    k_route<<<1, 1024>>>(t, scales, shifta, shiftb);

    dim3 g1(DHID / BN, (BATCH + BM - 1) / BM, NUM_E);
    k_gemm1<<<g1, 256, SMEM_BYTES>>>(y, W1, b1);

    dim3 g2(DIM / BN, (BATCH + BM - 1) / BM, NUM_E);
    k_gemm2<<<g2, 256, SMEM_BYTES>>>(y, W2, b2, out);
}